// round 15
// baseline (speedup 1.0000x reference)
#include <cuda_runtime.h>
#include <cuda_fp16.h>
#include <math.h>
#include <stdint.h>

// ---------------------------------------------------------------------------
// TransformerBlock B=4 L=2048 HID=1024 HEADS=16 HD=64 EXPAND=4096 (post-norm)
// Round 13: pure fp16 single-MMA everywhere (activation-lo dropped).
//   GEMM: C = fp16(A) @ fp16(B), 1 MMA/frag, fp32 accum, 4-stage cp.async.
//   Flash: Q K^T 1 MMA, P V 1 MMA.
// Error budget ~2e-4 (vs 1e-3 gate); R12 measured 1.33e-4 with weight-only
// rounding, activation side adds ~x sqrt(2).
// ---------------------------------------------------------------------------

#define MTOT   8192
#define SEQL   2048
#define HID    1024
#define EXPAND 4096

typedef __half fp16;

__device__ float g_a[(size_t)MTOT * HID];        // res2
__device__ float g_r[(size_t)MTOT * HID];        // res1
__device__ float g_h[(size_t)MTOT * HID];        // h
__device__ fp16 g_ah[(size_t)MTOT * HID];        // act fp16 (x / attn / h)
__device__ fp16 g_fh[(size_t)MTOT * EXPAND];     // qkv fp16, then ff fp16
#define WOFF_P (3072 * 1024)
#define WOFF_1 (WOFF_P + 1024 * 1024)
#define WOFF_2 (WOFF_1 + 4096 * 1024)
#define WTOT   (WOFF_2 + 1024 * 4096)
__device__ fp16 g_wh[(size_t)WTOT];              // weight^T fp16 [N][K]

enum { EPI_QKV = 0, EPI_GELU = 1, EPI_RES = 2 };

// ---------------------------------------------------------------------------
__device__ __forceinline__ void cp16s(uint32_t daddr, const void* g) {
    asm volatile("cp.async.cg.shared.global [%0], [%1], 16;\n" :: "r"(daddr), "l"(g));
}
__device__ __forceinline__ void cp_commit() { asm volatile("cp.async.commit_group;\n"); }
__device__ __forceinline__ void cp_wait_all() { asm volatile("cp.async.wait_group 0;\n"); }
__device__ __forceinline__ void cp_wait_1()   { asm volatile("cp.async.wait_group 1;\n"); }
__device__ __forceinline__ void cp_wait_2()   { asm volatile("cp.async.wait_group 2;\n"); }
__device__ __forceinline__ uint32_t smem_u32(const void* p) {
    uint32_t a;
    asm("{ .reg .u64 t; cvta.to.shared.u64 t, %1; cvt.u32.u64 %0, t; }" : "=r"(a) : "l"(p));
    return a;
}
__device__ __forceinline__ void ldm_x4(uint32_t* r, uint32_t addr) {
    asm volatile("ldmatrix.sync.aligned.m8n8.x4.shared.b16 {%0,%1,%2,%3}, [%4];"
                 : "=r"(r[0]), "=r"(r[1]), "=r"(r[2]), "=r"(r[3]) : "r"(addr));
}
__device__ __forceinline__ void ldm_x4_t(uint32_t* r, uint32_t addr) {
    asm volatile("ldmatrix.sync.aligned.m8n8.x4.trans.shared.b16 {%0,%1,%2,%3}, [%4];"
                 : "=r"(r[0]), "=r"(r[1]), "=r"(r[2]), "=r"(r[3]) : "r"(addr));
}
__device__ __forceinline__ void mma_f16(float* c, const uint32_t* a, const uint32_t* b) {
    asm volatile(
        "mma.sync.aligned.m16n8k16.row.col.f32.f16.f16.f32 "
        "{%0,%1,%2,%3}, {%4,%5,%6,%7}, {%8,%9}, {%0,%1,%2,%3};\n"
        : "+f"(c[0]), "+f"(c[1]), "+f"(c[2]), "+f"(c[3])
        : "r"(a[0]), "r"(a[1]), "r"(a[2]), "r"(a[3]), "r"(b[0]), "r"(b[1]));
}
__device__ __forceinline__ uint32_t packh(float v0, float v1) {
    __half2 p = __floats2half2_rn(v0, v1);
    return *(uint32_t*)&p;
}

// ---------------------------------------------------------------------------
// fp32 -> fp16 convert (for x)
// ---------------------------------------------------------------------------
__global__ void __launch_bounds__(256)
cvt_act(const float* __restrict__ X, fp16* __restrict__ H)
{
    size_t i = ((size_t)blockIdx.x * 256 + threadIdx.x) * 4;
    float4 v = *(const float4*)(X + i);
    *(uint2*)(H + i) = make_uint2(packh(v.x, v.y), packh(v.z, v.w));
}

// Weight transpose: W[K][N] fp32 -> [N][K] fp16
__global__ void __launch_bounds__(256)
wsplitT(const float* __restrict__ W, fp16* __restrict__ TH, int K, int N)
{
    __shared__ float s[32][33];
    const int tx = threadIdx.x & 31, ty = threadIdx.x >> 5;
    const int n0 = blockIdx.x * 32, k0 = blockIdx.y * 32;
#pragma unroll
    for (int i = 0; i < 4; i++)
        s[ty + 8 * i][tx] = W[(size_t)(k0 + ty + 8 * i) * N + n0 + tx];
    __syncthreads();
#pragma unroll
    for (int i = 0; i < 4; i++)
        TH[(size_t)(n0 + ty + 8 * i) * K + k0 + tx] = __float2half_rn(s[tx][ty + 8 * i]);
}

// ---------------------------------------------------------------------------
// fp16 MMA GEMM: CTA tile 256x128, BK=32, 8 warps (4m x 2n), warp tile 64x64.
// Single MMA per fragment, fp32 accum. 4-stage cp.async pipeline.
// ---------------------------------------------------------------------------
#define TSA_B  20480                 // 256 rows * 80B
#define TSB_B  10240                 // 128 rows * 80B
#define STG_B  (TSA_B + TSB_B)       // 30720
#define NSTAGE 4
#define GEMM_SMEM (NSTAGE * STG_B)   // 122880

template <int EPI>
__global__ void __launch_bounds__(256, 1)
tc_gemm(const fp16* __restrict__ Ah, const fp16* __restrict__ Bh,
        const float* __restrict__ bias, const float* __restrict__ R,
        float* __restrict__ C, fp16* __restrict__ FH,
        int N, int K)
{
    extern __shared__ char smem[];
    const uint32_t sb = smem_u32(smem);
    const int tid  = threadIdx.x;
    const int lane = tid & 31;
    const int wid  = tid >> 5;
    const int wm   = wid >> 1;        // 0..3 (64 rows each)
    const int wn   = wid & 1;         // 0..1 (64 cols each)
    const int bm   = blockIdx.y * 256;
    const int bn   = blockIdx.x * 128;
    const int g4   = lane >> 2;
    const int t4   = lane & 3;
    const int nk   = K / 32;

    float acc[4][8][4];
#pragma unroll
    for (int mt = 0; mt < 4; mt++)
#pragma unroll
        for (int nt = 0; nt < 8; nt++)
#pragma unroll
            for (int i = 0; i < 4; i++) acc[mt][nt][i] = 0.0f;

    auto load_tiles = [&](int kc, int buf) {
        const uint32_t base = sb + buf * STG_B;
        const int k0 = kc * 32;
#pragma unroll
        for (int i = 0; i < 4; i++) {
            int idx = tid + i * 256;
            int row = idx >> 2, ch = idx & 3;
            cp16s(base + row * 80 + ch * 16,
                  Ah + (size_t)(bm + row) * K + k0 + ch * 8);
        }
#pragma unroll
        for (int i = 0; i < 2; i++) {
            int idx = tid + i * 256;
            int row = idx >> 2, ch = idx & 3;
            cp16s(base + TSA_B + row * 80 + ch * 16,
                  Bh + (size_t)(bn + row) * K + k0 + ch * 8);
        }
    };

    const uint32_t aoff = (uint32_t)((lane & 15) * 80 + (lane >> 4) * 16);
    const uint32_t boff = (uint32_t)(((lane & 7) + ((lane >> 4) << 3)) * 80 +
                                     (((lane >> 3) & 1) * 16));

    load_tiles(0, 0);
    cp_commit();
    load_tiles(1, 1);
    cp_commit();
    load_tiles(2, 2);
    cp_commit();

    for (int kc = 0; kc < nk; kc++) {
        if (kc >= nk - 1) cp_wait_all();
        else if (kc == nk - 2) cp_wait_1();
        else cp_wait_2();
        __syncthreads();
        if (kc + 3 < nk) {
            load_tiles(kc + 3, (kc + 3) % NSTAGE);
            cp_commit();
        }
        const uint32_t bufb = sb + (kc % NSTAGE) * STG_B;
        const uint32_t pAh = bufb;
        const uint32_t pBh = bufb + TSA_B;

#pragma unroll
        for (int step = 0; step < 2; step++) {
            const uint32_t ks = step * 32;
            uint32_t ahf[4][4];
#pragma unroll
            for (int mt = 0; mt < 4; mt++)
                ldm_x4(ahf[mt], pAh + (wm * 64 + mt * 16) * 80 + aoff + ks);
            uint32_t bhf[4][4];
#pragma unroll
            for (int q = 0; q < 4; q++)
                ldm_x4(bhf[q], pBh + (wn * 64 + q * 16) * 80 + boff + ks);
#pragma unroll
            for (int mt = 0; mt < 4; mt++)
#pragma unroll
                for (int nt = 0; nt < 8; nt++)
                    mma_f16(acc[mt][nt], ahf[mt], &bhf[nt >> 1][(nt & 1) * 2]);
        }
    }

#pragma unroll
    for (int mt = 0; mt < 4; mt++) {
        int row0 = bm + wm * 64 + mt * 16 + g4;
#pragma unroll
        for (int nt = 0; nt < 8; nt++) {
            int col = bn + wn * 64 + nt * 8 + t4 * 2;
            float2 bv = *(const float2*)(bias + col);
#pragma unroll
            for (int half = 0; half < 2; half++) {
                int r = row0 + half * 8;
                float v0 = acc[mt][nt][half * 2 + 0] + bv.x;
                float v1 = acc[mt][nt][half * 2 + 1] + bv.y;
                if (EPI == EPI_QKV) {
                    float sc = (col < HID) ? 0.125f : 1.0f;
                    *(uint32_t*)(FH + (size_t)r * N + col) = packh(v0 * sc, v1 * sc);
                } else if (EPI == EPI_GELU) {
                    v0 = 0.5f * v0 * (1.0f + erff(v0 * 0.70710678118654752f));
                    v1 = 0.5f * v1 * (1.0f + erff(v1 * 0.70710678118654752f));
                    *(uint32_t*)(FH + (size_t)r * N + col) = packh(v0, v1);
                } else {
                    float2 rv = *(const float2*)(R + (size_t)r * N + col);
                    *(float2*)(C + (size_t)r * N + col) =
                        make_float2(v0 + rv.x, v1 + rv.y);
                }
            }
        }
    }
}

// ---------------------------------------------------------------------------
// Flash attention fp16: S = Q K^T (1 MMA), P fp16, O += P V (1 MMA).
// Grid (SEQL/128, B*HEADS), 8 warps; q pre-scaled by 1/8 at qkv epilogue.
// ---------------------------------------------------------------------------
#define QT_B   20480                 // 2 chunks * 128 rows * 80B
#define KT_B   10240                 // 2 chunks * 64 rows * 80B
#define KVBUF  (2 * KT_B)            // Kh, Vh
#define FL_SMEM (QT_B + 2 * KVBUF)   // 61440

__global__ void __launch_bounds__(256, 1)
flash_mma(const fp16* __restrict__ QKVH, fp16* __restrict__ OH)
{
    extern __shared__ char smem[];
    const uint32_t sb = smem_u32(smem);
    const int tid  = threadIdx.x;
    const int lane = tid & 31;
    const int wm   = tid >> 5;        // 0..7
    const int g4   = lane >> 2;
    const int t4   = lane & 3;
    const int qt   = blockIdx.x;      // 16 q-tiles
    const int b    = blockIdx.y >> 4;
    const int h    = blockIdx.y & 15;

    const size_t rowbase = (size_t)b * SEQL * 3072;
    const fp16* QHg = QKVH + rowbase + (size_t)qt * 128 * 3072 + h * 64;
    const fp16* KHg = QKVH + rowbase + 1024 + h * 64;
    const fp16* VHg = QKVH + rowbase + 2048 + h * 64;

    const uint32_t sqh = sb;
    const uint32_t skv = sb + QT_B;

#pragma unroll
    for (int i = 0; i < 4; i++) {
        int idx = tid + i * 256;
        int row = idx >> 3, c = idx & 7;
        uint32_t d = (c >> 2) * 10240 + row * 80 + (c & 3) * 16;
        cp16s(sqh + d, QHg + (size_t)row * 3072 + c * 8);
    }

    auto stage_kv = [&](int kt, int buf) {
        const uint32_t base = skv + buf * KVBUF;
        const int key0 = kt * 64;
#pragma unroll
        for (int i = 0; i < 2; i++) {
            int idx = tid + i * 256;
            int row = idx >> 3, c = idx & 7;
            uint32_t d = (c >> 2) * 5120 + row * 80 + (c & 3) * 16;
            const size_t so = (size_t)(key0 + row) * 3072 + c * 8;
            cp16s(base + d,        KHg + so);
            cp16s(base + KT_B + d, VHg + so);
        }
    };

    stage_kv(0, 0);
    cp_commit();
    stage_kv(1, 1);
    cp_commit();

    const uint32_t qoff = (uint32_t)((lane & 15) * 80 + (lane >> 4) * 16);
    const uint32_t koff = (uint32_t)(((lane & 7) + ((lane >> 4) << 3)) * 80 +
                                     (((lane >> 3) & 1) * 16));

    uint32_t qhf[4][4];
    float O[8][4];
#pragma unroll
    for (int t = 0; t < 8; t++)
#pragma unroll
        for (int i = 0; i < 4; i++) O[t][i] = 0.0f;
    float m0 = -3.0e38f, m1 = -3.0e38f, l0 = 0.0f, l1 = 0.0f;

    const int nt = SEQL / 64;
    for (int kt = 0; kt < nt; kt++) {
        if (kt == nt - 1) cp_wait_all(); else cp_wait_1();
        __syncthreads();
        if (kt == 0) {
#pragma unroll
            for (int ds = 0; ds < 4; ds++)
                ldm_x4(qhf[ds], sqh + (ds >> 1) * 10240 + (wm * 16) * 80 + qoff + (ds & 1) * 32);
        }
        const uint32_t kb = skv + (kt & 1) * KVBUF;

        // ---- S = Q K^T ----
        float S[8][4];
#pragma unroll
        for (int t = 0; t < 8; t++)
#pragma unroll
            for (int i = 0; i < 4; i++) S[t][i] = 0.0f;

#pragma unroll
        for (int ds = 0; ds < 4; ds++) {
#pragma unroll
            for (int p = 0; p < 4; p++) {
                uint32_t khf[4];
                ldm_x4(khf, kb + (ds >> 1) * 5120 + (p * 16) * 80 + koff + (ds & 1) * 32);
#pragma unroll
                for (int e = 0; e < 2; e++)
                    mma_f16(S[2 * p + e], qhf[ds], &khf[e * 2]);
            }
        }

        // ---- online softmax ----
        float mx0 = S[0][0], mx1 = S[0][2];
#pragma unroll
        for (int t = 0; t < 8; t++) {
            mx0 = fmaxf(mx0, fmaxf(S[t][0], S[t][1]));
            mx1 = fmaxf(mx1, fmaxf(S[t][2], S[t][3]));
        }
        mx0 = fmaxf(mx0, __shfl_xor_sync(0xffffffffu, mx0, 1));
        mx0 = fmaxf(mx0, __shfl_xor_sync(0xffffffffu, mx0, 2));
        mx1 = fmaxf(mx1, __shfl_xor_sync(0xffffffffu, mx1, 1));
        mx1 = fmaxf(mx1, __shfl_xor_sync(0xffffffffu, mx1, 2));
        float mn0 = fmaxf(m0, mx0), mn1 = fmaxf(m1, mx1);
        float al0 = __expf(m0 - mn0), al1 = __expf(m1 - mn1);
        m0 = mn0; m1 = mn1;
        float rs0 = 0.0f, rs1 = 0.0f;
#pragma unroll
        for (int t = 0; t < 8; t++) {
            S[t][0] = __expf(S[t][0] - mn0);
            S[t][1] = __expf(S[t][1] - mn0);
            S[t][2] = __expf(S[t][2] - mn1);
            S[t][3] = __expf(S[t][3] - mn1);
            rs0 += S[t][0] + S[t][1];
            rs1 += S[t][2] + S[t][3];
        }
        rs0 += __shfl_xor_sync(0xffffffffu, rs0, 1);
        rs0 += __shfl_xor_sync(0xffffffffu, rs0, 2);
        rs1 += __shfl_xor_sync(0xffffffffu, rs1, 1);
        rs1 += __shfl_xor_sync(0xffffffffu, rs1, 2);
        l0 = l0 * al0 + rs0;
        l1 = l1 * al1 + rs1;
#pragma unroll
        for (int t = 0; t < 8; t++) {
            O[t][0] *= al0; O[t][1] *= al0;
            O[t][2] *= al1; O[t][3] *= al1;
        }

        uint32_t pk[8][2];
#pragma unroll
        for (int t = 0; t < 8; t++) {
            pk[t][0] = packh(S[t][0], S[t][1]);
            pk[t][1] = packh(S[t][2], S[t][3]);
        }

        // ---- O += P V ----
#pragma unroll
        for (int k4 = 0; k4 < 4; k4++) {
            uint32_t pa[4] = {pk[2 * k4][0], pk[2 * k4][1],
                              pk[2 * k4 + 1][0], pk[2 * k4 + 1][1]};
#pragma unroll
            for (int p = 0; p < 4; p++) {
                uint32_t vhf[4];
                uint32_t ro = (p >> 1) * 5120 +
                              (16 * k4 + (lane & 15)) * 80 +
                              ((p & 1) * 16 + 8 * (lane >> 4)) * 2;
                ldm_x4_t(vhf, kb + KT_B + ro);
#pragma unroll
                for (int e = 0; e < 2; e++)
                    mma_f16(O[2 * p + e], pa, &vhf[e * 2]);
            }
        }

        __syncthreads();
        if (kt + 2 < nt) {
            stage_kv(kt + 2, kt & 1);
            cp_commit();
        }
    }

    float inv0 = 1.0f / l0, inv1 = 1.0f / l1;
    const int r0 = qt * 128 + wm * 16 + g4;
    const size_t ob = ((size_t)b * SEQL) * HID + (size_t)h * 64;
#pragma unroll
    for (int t = 0; t < 8; t++) {
        int col = t * 8 + 2 * t4;
        *(uint32_t*)(OH + ob + (size_t)r0 * HID + col) =
            packh(O[t][0] * inv0, O[t][1] * inv0);
        *(uint32_t*)(OH + ob + (size_t)(r0 + 8) * HID + col) =
            packh(O[t][2] * inv1, O[t][3] * inv1);
    }
}

// ---------------------------------------------------------------------------
template <bool SPLIT>
__global__ void __launch_bounds__(256)
layernorm_kernel(const float* __restrict__ X, const float* __restrict__ g,
                 const float* __restrict__ be, float* __restrict__ Y,
                 fp16* __restrict__ YH)
{
    __shared__ float s_s[8], s_q[8];
    const int row = blockIdx.x;
    const int tid = threadIdx.x;
    const int lane = tid & 31, wid = tid >> 5;

    float4 v = *(const float4*)(X + (size_t)row * HID + tid * 4);
    float s  = v.x + v.y + v.z + v.w;
    float ss = v.x * v.x + v.y * v.y + v.z * v.z + v.w * v.w;
#pragma unroll
    for (int off = 16; off >= 1; off >>= 1) {
        s  += __shfl_xor_sync(0xffffffffu, s, off);
        ss += __shfl_xor_sync(0xffffffffu, ss, off);
    }
    if (lane == 0) { s_s[wid] = s; s_q[wid] = ss; }
    __syncthreads();
    float ts = 0.0f, tq = 0.0f;
#pragma unroll
    for (int w = 0; w < 8; w++) { ts += s_s[w]; tq += s_q[w]; }

    float mean = ts * (1.0f / 1024.0f);
    float var  = tq * (1.0f / 1024.0f) - mean * mean;
    float rstd = rsqrtf(var + 1e-5f);

    float4 gv = *(const float4*)(g + tid * 4);
    float4 bv = *(const float4*)(be + tid * 4);
    float4 o;
    o.x = (v.x - mean) * rstd * gv.x + bv.x;
    o.y = (v.y - mean) * rstd * gv.y + bv.y;
    o.z = (v.z - mean) * rstd * gv.z + bv.z;
    o.w = (v.w - mean) * rstd * gv.w + bv.w;
    *(float4*)(Y + (size_t)row * HID + tid * 4) = o;
    if (SPLIT) {
        size_t off = (size_t)row * HID + tid * 4;
        *(uint2*)(YH + off) = make_uint2(packh(o.x, o.y), packh(o.z, o.w));
    }
}

// ---------------------------------------------------------------------------
extern "C" void kernel_launch(void* const* d_in, const int* in_sizes, int n_in,
                              void* d_out, int out_size)
{
    const float* x     = (const float*)d_in[0];
    const float* Wqkv  = (const float*)d_in[1];
    const float* bqkv  = (const float*)d_in[2];
    const float* Wproj = (const float*)d_in[3];
    const float* bproj = (const float*)d_in[4];
    const float* W1    = (const float*)d_in[5];
    const float* b1    = (const float*)d_in[6];
    const float* W2    = (const float*)d_in[7];
    const float* b2    = (const float*)d_in[8];
    const float* g1    = (const float*)d_in[9];
    const float* be1   = (const float*)d_in[10];
    const float* g2    = (const float*)d_in[11];
    const float* be2   = (const float*)d_in[12];
    float* out = (float*)d_out;

    float *res2, *res1, *hbuf;
    fp16 *ah, *fh, *wh;
    cudaGetSymbolAddress((void**)&res2, g_a);
    cudaGetSymbolAddress((void**)&res1, g_r);
    cudaGetSymbolAddress((void**)&hbuf, g_h);
    cudaGetSymbolAddress((void**)&ah,   g_ah);
    cudaGetSymbolAddress((void**)&fh,   g_fh);
    cudaGetSymbolAddress((void**)&wh,   g_wh);

    static bool attr_done = false;
    if (!attr_done) {
        cudaFuncSetAttribute(tc_gemm<EPI_QKV>,  cudaFuncAttributeMaxDynamicSharedMemorySize, GEMM_SMEM);
        cudaFuncSetAttribute(tc_gemm<EPI_GELU>, cudaFuncAttributeMaxDynamicSharedMemorySize, GEMM_SMEM);
        cudaFuncSetAttribute(tc_gemm<EPI_RES>,  cudaFuncAttributeMaxDynamicSharedMemorySize, GEMM_SMEM);
        cudaFuncSetAttribute(flash_mma, cudaFuncAttributeMaxDynamicSharedMemorySize, FL_SMEM);
        attr_done = true;
    }

    // weight transpose (fp16)
    wsplitT<<<dim3(3072 / 32, 1024 / 32), 256>>>(Wqkv, wh, HID, 3 * HID);
    wsplitT<<<dim3(1024 / 32, 1024 / 32), 256>>>(Wproj, wh + WOFF_P, HID, HID);
    wsplitT<<<dim3(4096 / 32, 1024 / 32), 256>>>(W1, wh + WOFF_1, HID, EXPAND);
    wsplitT<<<dim3(1024 / 32, 4096 / 32), 256>>>(W2, wh + WOFF_2, EXPAND, HID);

    // 1) qkv = x @ Wqkv + bqkv  -> fp16, q pre-scaled by 1/8
    cvt_act<<<(MTOT * HID) / 1024, 256>>>(x, ah);
    tc_gemm<EPI_QKV><<<dim3(3 * HID / 128, MTOT / 256), 256, GEMM_SMEM>>>(
        ah, wh, bqkv, nullptr, nullptr, fh, 3 * HID, HID);

    // 2) attn = flash(qkv) -> fp16 into ah
    flash_mma<<<dim3(SEQL / 128, 4 * 16), 256, FL_SMEM>>>(fh, ah);

    // 3) res1 = attn @ Wproj + bproj + x
    tc_gemm<EPI_RES><<<dim3(HID / 128, MTOT / 256), 256, GEMM_SMEM>>>(
        ah, wh + WOFF_P, bproj, x, res1, nullptr, HID, HID);

    // 4) h = LN(res1) (+ fp16 convert)
    layernorm_kernel<true><<<MTOT, 256>>>(res1, g1, be1, hbuf, ah);

    // 5) ff = gelu(h @ W1 + b1) -> fp16
    tc_gemm<EPI_GELU><<<dim3(EXPAND / 128, MTOT / 256), 256, GEMM_SMEM>>>(
        ah, wh + WOFF_1, b1, nullptr, nullptr, fh, EXPAND, HID);

    // 6) res2 = ff @ W2 + b2 + h
    tc_gemm<EPI_RES><<<dim3(HID / 128, MTOT / 256), 256, GEMM_SMEM>>>(
        fh, wh + WOFF_2, b2, hbuf, res2, nullptr, HID, EXPAND);

    // 7) out = LN(res2)
    layernorm_kernel<false><<<MTOT, 256>>>(res2, g2, be2, out, nullptr);
}